// round 6
// baseline (speedup 1.0000x reference)
#include <cuda_runtime.h>

#define B_ 2
#define N_ 2048
#define C_ 1024
#define H_ 16
#define D_ 64
#define SCALE_ 0.125f
#define M_TOT (B_ * N_)

// ---------------- scratch (device globals; no allocation) ----------------
__device__ float g_qkv[(size_t)M_TOT * 3 * C_];   // [B*N, 3C]
__device__ float g_s[(size_t)M_TOT * C_];         // e @ W_s
__device__ float g_gate[(size_t)M_TOT * C_];      // x @ W_gate
__device__ float g_att[(size_t)M_TOT * C_];       // gated attention output

// ---------------- classic tiled SGEMM: C = A[MxK] * B[KxN] (+bias) -------
// 128x128 tile, BK=8, 256 threads, 8x8 per-thread microtile.
template <int BIAS>
__global__ __launch_bounds__(256, 2) void sgemm(
    const float* __restrict__ A, const float* __restrict__ Bm,
    const float* __restrict__ bias, float* __restrict__ Cm,
    int M, int Nn, int K)
{
    __shared__ float As[8][128];
    __shared__ float Bs[8][128];

    const int tid = threadIdx.x;
    const int tx = tid & 15, ty = tid >> 4;
    const int m0 = blockIdx.y * 128;
    const int n0 = blockIdx.x * 128;

    // load mapping
    const int arow = tid >> 1;          // 0..127
    const int acg  = (tid & 1) * 4;     // 0 or 4
    const int brow = tid >> 5;          // 0..7
    const int bcol = (tid & 31) * 4;    // 0..124

    const float* Aptr = A + (size_t)(m0 + arow) * K + acg;
    const float* Bptr = Bm + (size_t)brow * Nn + n0 + bcol;

    float acc[8][8];
#pragma unroll
    for (int i = 0; i < 8; i++)
#pragma unroll
        for (int j = 0; j < 8; j++) acc[i][j] = 0.f;

    for (int k0 = 0; k0 < K; k0 += 8) {
        float4 av = *(const float4*)(Aptr + k0);
        float4 bv = *(const float4*)(Bptr + (size_t)k0 * Nn);
        As[acg + 0][arow] = av.x;
        As[acg + 1][arow] = av.y;
        As[acg + 2][arow] = av.z;
        As[acg + 3][arow] = av.w;
        *(float4*)&Bs[brow][bcol] = bv;
        __syncthreads();
#pragma unroll
        for (int k = 0; k < 8; k++) {
            float a[8], b[8];
            *(float4*)&a[0] = *(const float4*)&As[k][ty * 8];
            *(float4*)&a[4] = *(const float4*)&As[k][ty * 8 + 4];
            *(float4*)&b[0] = *(const float4*)&Bs[k][tx * 8];
            *(float4*)&b[4] = *(const float4*)&Bs[k][tx * 8 + 4];
#pragma unroll
            for (int i = 0; i < 8; i++)
#pragma unroll
                for (int j = 0; j < 8; j++)
                    acc[i][j] = fmaf(a[i], b[j], acc[i][j]);
        }
        __syncthreads();
    }

#pragma unroll
    for (int i = 0; i < 8; i++) {
        float* cp = Cm + (size_t)(m0 + ty * 8 + i) * Nn + n0 + tx * 8;
#pragma unroll
        for (int j4 = 0; j4 < 2; j4++) {
            float4 v;
            v.x = acc[i][j4 * 4 + 0];
            v.y = acc[i][j4 * 4 + 1];
            v.z = acc[i][j4 * 4 + 2];
            v.w = acc[i][j4 * 4 + 3];
            if (BIAS) {
                const float* bp = bias + n0 + tx * 8 + j4 * 4;
                v.x += bp[0]; v.y += bp[1]; v.z += bp[2]; v.w += bp[3];
            }
            *(float4*)(cp + j4 * 4) = v;
        }
    }
}

// ---------------- fused flash attention --------------------------------
// grid: (N/64, H, B), 256 threads. Q tile 64 rows; loop KV tiles of 64.
// smem: QsT[64][64] (d-major), KsT[64][64] (d-major; reused as P[qr][kc]),
//       Vs[64][64] (row-major). 3*16KB = 48KB dynamic.
__global__ __launch_bounds__(256) void flash(
    const float* __restrict__ qkv, const float* __restrict__ sb,
    const float* __restrict__ gate, float* __restrict__ outp)
{
    extern __shared__ float sm[];
    float* QsT = sm;              // [d][r], stride 64
    float* KsT = sm + 64 * 64;    // [d][r]; later P[qr][kc]
    float* Vs  = sm + 2 * 64 * 64;// [r][d]

    const int qt = blockIdx.x, h = blockIdx.y, b = blockIdx.z;
    const int tid = threadIdx.x;
    const int tx = tid & 15, ty = tid >> 4;
    const int qr0 = ty * 4;   // this thread's 4 q-rows
    const int kc0 = tx * 4;   // this thread's 4 k-cols (scores)
    const int dc0 = tx * 4;   // this thread's 4 out-dims

    // ---- load Q tile transposed, pre-scaled ----
#pragma unroll
    for (int li = 0; li < 4; li++) {
        int f = tid + 256 * li;          // 0..1023
        int r = f & 63;                  // lanes -> consecutive rows: conflict-free smem stores
        int d4 = f >> 6;                 // 0..15
        const float4 v = *(const float4*)(
            qkv + (size_t)(b * N_ + qt * 64 + r) * (3 * C_) + h * D_ + d4 * 4);
        QsT[(d4 * 4 + 0) * 64 + r] = v.x * SCALE_;
        QsT[(d4 * 4 + 1) * 64 + r] = v.y * SCALE_;
        QsT[(d4 * 4 + 2) * 64 + r] = v.z * SCALE_;
        QsT[(d4 * 4 + 3) * 64 + r] = v.w * SCALE_;
    }

    float m_i[4], l_i[4], acc[4][4];
#pragma unroll
    for (int i = 0; i < 4; i++) {
        m_i[i] = -1e30f; l_i[i] = 0.f;
#pragma unroll
        for (int j = 0; j < 4; j++) acc[i][j] = 0.f;
    }

    for (int kt = 0; kt < N_ / 64; kt++) {
        __syncthreads();  // prev PV done reading Vs/P before overwrite (and Q visible on iter 0)

        // ---- load K+S transposed, V row-major ----
#pragma unroll
        for (int li = 0; li < 4; li++) {
            int f = tid + 256 * li;
            int r = f & 63;
            int d4 = f >> 6;
            size_t grow = (size_t)(b * N_ + kt * 64 + r);
            const float4 kv = *(const float4*)(qkv + grow * (3 * C_) + C_ + h * D_ + d4 * 4);
            const float4 sv = *(const float4*)(sb + grow * C_ + h * D_ + d4 * 4);
            KsT[(d4 * 4 + 0) * 64 + r] = kv.x + sv.x;
            KsT[(d4 * 4 + 1) * 64 + r] = kv.y + sv.y;
            KsT[(d4 * 4 + 2) * 64 + r] = kv.z + sv.z;
            KsT[(d4 * 4 + 3) * 64 + r] = kv.w + sv.w;
        }
#pragma unroll
        for (int li = 0; li < 4; li++) {
            int f = tid + 256 * li;
            int r = f >> 4;              // coalesced gmem, aligned float4 smem store
            int d4 = f & 15;
            size_t grow = (size_t)(b * N_ + kt * 64 + r);
            const float4 vv = *(const float4*)(qkv + grow * (3 * C_) + 2 * C_ + h * D_ + d4 * 4);
            *(float4*)(Vs + r * 64 + d4 * 4) = vv;
        }
        __syncthreads();

        // ---- scores: sc[i][j] = q_i . (k+s)_j  (scale folded into Q) ----
        float sc[4][4];
#pragma unroll
        for (int i = 0; i < 4; i++)
#pragma unroll
            for (int j = 0; j < 4; j++) sc[i][j] = 0.f;

#pragma unroll 4
        for (int kk = 0; kk < 64; kk++) {
            float4 q4 = *(const float4*)(QsT + kk * 64 + qr0);
            float4 k4 = *(const float4*)(KsT + kk * 64 + kc0);
            float qa[4] = {q4.x, q4.y, q4.z, q4.w};
            float ka[4] = {k4.x, k4.y, k4.z, k4.w};
#pragma unroll
            for (int i = 0; i < 4; i++)
#pragma unroll
                for (int j = 0; j < 4; j++)
                    sc[i][j] = fmaf(qa[i], ka[j], sc[i][j]);
        }
        __syncthreads();  // everyone done reading KsT before it becomes P

        // ---- online softmax; write P into KsT buffer ----
#pragma unroll
        for (int i = 0; i < 4; i++) {
            float tm = fmaxf(fmaxf(sc[i][0], sc[i][1]), fmaxf(sc[i][2], sc[i][3]));
#pragma unroll
            for (int o = 8; o >= 1; o >>= 1)
                tm = fmaxf(tm, __shfl_xor_sync(0xffffffffu, tm, o));
            float mn = fmaxf(m_i[i], tm);
            float cf = __expf(m_i[i] - mn);
            m_i[i] = mn;
            float rs = 0.f;
#pragma unroll
            for (int j = 0; j < 4; j++) {
                sc[i][j] = __expf(sc[i][j] - mn);
                rs += sc[i][j];
            }
#pragma unroll
            for (int o = 8; o >= 1; o >>= 1)
                rs += __shfl_xor_sync(0xffffffffu, rs, o);
            l_i[i] = l_i[i] * cf + rs;
#pragma unroll
            for (int j = 0; j < 4; j++) acc[i][j] *= cf;
#pragma unroll
            for (int j = 0; j < 4; j++)
                KsT[(qr0 + i) * 64 + kc0 + j] = sc[i][j];  // P[qr][kc]
        }
        __syncthreads();

        // ---- PV: acc[i][d] += P[qr0+i][j] * V[j][dc0+d] ----
#pragma unroll 2
        for (int j = 0; j < 64; j++) {
            float4 v4 = *(const float4*)(Vs + j * 64 + dc0);
            float va[4] = {v4.x, v4.y, v4.z, v4.w};
            float pa[4];
#pragma unroll
            for (int i = 0; i < 4; i++) pa[i] = KsT[(qr0 + i) * 64 + j];
#pragma unroll
            for (int i = 0; i < 4; i++)
#pragma unroll
                for (int jd = 0; jd < 4; jd++)
                    acc[i][jd] = fmaf(pa[i], va[jd], acc[i][jd]);
        }
    }

    // ---- epilogue: normalize, multiply by gate, write ----
#pragma unroll
    for (int i = 0; i < 4; i++) {
        size_t row = (size_t)(b * N_ + qt * 64 + qr0 + i);
        float inv = 1.f / l_i[i];
        const float4 g4 = *(const float4*)(gate + row * C_ + h * D_ + dc0);
        float4 o;
        o.x = acc[i][0] * inv * g4.x;
        o.y = acc[i][1] * inv * g4.y;
        o.z = acc[i][2] * inv * g4.z;
        o.w = acc[i][3] * inv * g4.w;
        *(float4*)(outp + row * C_ + h * D_ + dc0) = o;
    }
}

// ---------------- launch ------------------------------------------------
extern "C" void kernel_launch(void* const* d_in, const int* in_sizes, int n_in,
                              void* d_out, int out_size)
{
    (void)in_sizes; (void)n_in; (void)out_size;
    const float* x    = (const float*)d_in[0];
    const float* e    = (const float*)d_in[1];
    const float* Wqkv = (const float*)d_in[2];
    const float* Ws   = (const float*)d_in[3];
    const float* Wg   = (const float*)d_in[4];
    const float* Wp   = (const float*)d_in[5];
    const float* bp   = (const float*)d_in[6];
    float* out = (float*)d_out;

    float *qkv, *s, *gate, *att;
    cudaGetSymbolAddress((void**)&qkv,  g_qkv);
    cudaGetSymbolAddress((void**)&s,    g_s);
    cudaGetSymbolAddress((void**)&gate, g_gate);
    cudaGetSymbolAddress((void**)&att,  g_att);

    // qkv = x @ W_qkv
    sgemm<0><<<dim3((3 * C_) / 128, M_TOT / 128), 256>>>(x, Wqkv, nullptr, qkv, M_TOT, 3 * C_, C_);
    // gate = x @ W_gate
    sgemm<0><<<dim3(C_ / 128, M_TOT / 128), 256>>>(x, Wg, nullptr, gate, M_TOT, C_, C_);
    // s = e @ W_s
    sgemm<0><<<dim3(C_ / 128, M_TOT / 128), 256>>>(e, Ws, nullptr, s, M_TOT, C_, C_);

    // fused flash attention (k+s fold, scale fold, gate fold)
    flash<<<dim3(N_ / 64, H_, B_), 256, 3 * 64 * 64 * sizeof(float)>>>(qkv, s, gate, att);

    // out = att @ W_proj + b_proj
    sgemm<1><<<dim3(C_ / 128, M_TOT / 128), 256>>>(att, Wp, bp, out, M_TOT, C_, C_);
}

// round 7
// speedup vs baseline: 2.6617x; 2.6617x over previous
#include <cuda_runtime.h>

#define B_ 2
#define N_ 2048
#define C_ 1024
#define H_ 16
#define D_ 64
#define SCALE_ 0.125f
#define M_TOT (B_ * N_)

// ---------------- scratch (device globals; no allocation) ----------------
__device__ float    g_qkv[(size_t)M_TOT * 3 * C_];   // [B*N, 3C]
__device__ float    g_s[(size_t)M_TOT * C_];         // e @ W_s
__device__ float    g_gate[(size_t)M_TOT * C_];      // x @ W_gate
__device__ float    g_att[(size_t)M_TOT * C_];       // gated attention output
__device__ unsigned g_wqkvT[(size_t)3 * C_ * C_];    // W_qkv^T as tf32 bits [3C][C]
__device__ unsigned g_wsT[(size_t)C_ * C_];
__device__ unsigned g_wgT[(size_t)C_ * C_];
__device__ unsigned g_wpT[(size_t)C_ * C_];

// ---------------- tf32 helpers ------------------------------------------
__device__ __forceinline__ unsigned f2tf32(float x) {
    unsigned y;
    asm("cvt.rna.tf32.f32 %0, %1;" : "=r"(y) : "f"(x));
    return y;
}

__device__ __forceinline__ void ldm_x4(unsigned r[4], const void* p) {
    unsigned a = (unsigned)__cvta_generic_to_shared(p);
    asm volatile("ldmatrix.sync.aligned.m8n8.x4.shared.b16 {%0,%1,%2,%3}, [%4];"
                 : "=r"(r[0]), "=r"(r[1]), "=r"(r[2]), "=r"(r[3]) : "r"(a));
}

__device__ __forceinline__ void mma_tf32(float c[4], const unsigned a[4], const unsigned b[2]) {
    asm volatile("mma.sync.aligned.m16n8k8.row.col.f32.tf32.tf32.f32 "
                 "{%0,%1,%2,%3}, {%4,%5,%6,%7}, {%8,%9}, {%0,%1,%2,%3};"
                 : "+f"(c[0]), "+f"(c[1]), "+f"(c[2]), "+f"(c[3])
                 : "r"(a[0]), "r"(a[1]), "r"(a[2]), "r"(a[3]), "r"(b[0]), "r"(b[1]));
}

// ---------------- weight transpose + tf32 convert: out[n][k]=in[k][n] ----
__global__ void transpose_cvt(const float* __restrict__ in, unsigned* __restrict__ out,
                              int K, int N)
{
    __shared__ float t[32][33];
    int bx = blockIdx.x * 32;   // n
    int by = blockIdx.y * 32;   // k
    int x = threadIdx.x;        // 0..31
    int y = threadIdx.y;        // 0..7
#pragma unroll
    for (int i = 0; i < 32; i += 8)
        t[y + i][x] = in[(size_t)(by + y + i) * N + bx + x];
    __syncthreads();
#pragma unroll
    for (int i = 0; i < 32; i += 8)
        out[(size_t)(bx + y + i) * K + by + x] = f2tf32(t[x][y + i]);
}

// ---------------- tf32 GEMM: C = A[M,K] * Bt[N,K]^T (+bias) --------------
// 128x128 tile, BK=32, 256 thr (8 warps, 2x4), warp tile 64x32.
template <int BIAS>
__global__ __launch_bounds__(256) void gemm_tf32(
    const float* __restrict__ A, const unsigned* __restrict__ Bt,
    const float* __restrict__ bias, float* __restrict__ Cm,
    int M, int Nn, int K)
{
    __shared__ unsigned As[128 * 36];
    __shared__ unsigned Bs[128 * 36];
    const int tid = threadIdx.x;
    const int wid = tid >> 5, lane = tid & 31;
    const int wm = (wid & 1) * 64, wn = (wid >> 1) * 32;
    const int m_blk = blockIdx.y * 128, n_blk = blockIdx.x * 128;

    const int lrow = tid >> 3;          // 0..31
    const int lcg  = (tid & 7) * 4;     // 0..28

    float4 pa[4]; uint4 pb[4];

    auto ldA = [&](int kb) {
#pragma unroll
        for (int it = 0; it < 4; it++)
            pa[it] = *(const float4*)(A + (size_t)(m_blk + it * 32 + lrow) * K + kb * 32 + lcg);
    };
    auto ldB = [&](int kb) {
#pragma unroll
        for (int it = 0; it < 4; it++)
            pb[it] = *(const uint4*)(Bt + (size_t)(n_blk + it * 32 + lrow) * K + kb * 32 + lcg);
    };
    auto stAB = [&] {
#pragma unroll
        for (int it = 0; it < 4; it++) {
            uint4 u;
            u.x = f2tf32(pa[it].x); u.y = f2tf32(pa[it].y);
            u.z = f2tf32(pa[it].z); u.w = f2tf32(pa[it].w);
            *(uint4*)&As[(it * 32 + lrow) * 36 + lcg] = u;
            *(uint4*)&Bs[(it * 32 + lrow) * 36 + lcg] = pb[it];
        }
    };

    float acc[4][4][4] = {};

    ldA(0); ldB(0);
    stAB();
    __syncthreads();

    const int KB = K / 32;
    for (int kb = 0; kb < KB; kb++) {
        if (kb + 1 < KB) { ldA(kb + 1); ldB(kb + 1); }
#pragma unroll
        for (int ks = 0; ks < 4; ks++) {
            unsigned af[4][4], bf[4][2];
#pragma unroll
            for (int mt = 0; mt < 4; mt++) {
                int row = wm + mt * 16 + (lane & 7) + ((lane & 8) ? 8 : 0);
                int col = ks * 8 + ((lane & 16) ? 4 : 0);
                ldm_x4(af[mt], &As[row * 36 + col]);
            }
#pragma unroll
            for (int p = 0; p < 2; p++) {
                int row = wn + p * 16 + (lane & 7) + ((lane & 16) ? 8 : 0);
                int col = ks * 8 + ((lane & 8) ? 4 : 0);
                unsigned tr[4];
                ldm_x4(tr, &Bs[row * 36 + col]);
                bf[p * 2 + 0][0] = tr[0]; bf[p * 2 + 0][1] = tr[1];
                bf[p * 2 + 1][0] = tr[2]; bf[p * 2 + 1][1] = tr[3];
            }
#pragma unroll
            for (int mt = 0; mt < 4; mt++)
#pragma unroll
                for (int nt = 0; nt < 4; nt++)
                    mma_tf32(acc[mt][nt], af[mt], bf[nt]);
        }
        __syncthreads();
        if (kb + 1 < KB) { stAB(); __syncthreads(); }
    }

    const int g = lane >> 2, t2 = (lane & 3) * 2;
#pragma unroll
    for (int mt = 0; mt < 4; mt++) {
#pragma unroll
        for (int nt = 0; nt < 4; nt++) {
            int col = n_blk + wn + nt * 8 + t2;
            float b0 = 0.f, b1 = 0.f;
            if (BIAS) { b0 = bias[col]; b1 = bias[col + 1]; }
            size_t r0 = (size_t)(m_blk + wm + mt * 16 + g);
            float2 v0 = { acc[mt][nt][0] + b0, acc[mt][nt][1] + b1 };
            float2 v1 = { acc[mt][nt][2] + b0, acc[mt][nt][3] + b1 };
            *(float2*)(Cm + r0 * Nn + col) = v0;
            *(float2*)(Cm + (r0 + 8) * Nn + col) = v1;
        }
    }
}

// ---------------- tensor-core flash attention ----------------------------
// grid (N/128, H, B), 256 thr (8 warps). Warp w owns q-rows 16w..16w+15,
// full kv range. Q frags in regs; P reuses the Q smem buffer (per-warp rows).
__global__ __launch_bounds__(256) void flash_tc(
    const float* __restrict__ qkv, const float* __restrict__ sb,
    const float* __restrict__ gate, float* __restrict__ outp)
{
    extern __shared__ unsigned sm[];
    unsigned* Qs = sm;                       // [128][68], reused as P (tf32)
    unsigned* Ks = sm + 128 * 68;            // [64 kv][68 d]
    unsigned* Vt = sm + 128 * 68 + 64 * 68;  // [64 d][68 kv]

    const int qt = blockIdx.x, h = blockIdx.y, b = blockIdx.z;
    const int tid = threadIdx.x;
    const int wid = tid >> 5, lane = tid & 31;
    const int g = lane >> 2, t = lane & 3;
    const size_t qbase = (size_t)(b * N_ + qt * 128);

    // ---- Q -> smem (scaled, tf32) ----
#pragma unroll
    for (int li = 0; li < 8; li++) {
        int f = tid + 256 * li;
        int r = f & 127, d4 = (f >> 7) * 4;
        float4 v = *(const float4*)(qkv + (qbase + r) * (3 * C_) + h * D_ + d4);
        uint4 u = { f2tf32(v.x * SCALE_), f2tf32(v.y * SCALE_),
                    f2tf32(v.z * SCALE_), f2tf32(v.w * SCALE_) };
        *(uint4*)&Qs[r * 68 + d4] = u;
    }
    __syncthreads();

    // ---- Q fragments -> registers (own 16 rows) ----
    unsigned qf[8][4];
    {
        int row = wid * 16 + (lane & 7) + ((lane & 8) ? 8 : 0);
        int cof = (lane & 16) ? 4 : 0;
#pragma unroll
        for (int kd = 0; kd < 8; kd++)
            ldm_x4(qf[kd], &Qs[row * 68 + kd * 8 + cof]);
    }

    float o[8][4] = {};
    float m0v = -1e30f, m1v = -1e30f, l0v = 0.f, l1v = 0.f;

    for (int kt = 0; kt < N_ / 64; kt++) {
        __syncthreads();   // all warps done with Ks (S) / Vt (PV) from prev iter
        const size_t kvb = (size_t)(b * N_ + kt * 64);

        // K + s fold, tf32, row-major [kv][d]
#pragma unroll
        for (int li = 0; li < 4; li++) {
            int f = tid + 256 * li;
            int r = f & 63, d4 = (f >> 6) * 4;
            float4 kv4 = *(const float4*)(qkv + (kvb + r) * (3 * C_) + C_ + h * D_ + d4);
            float4 sv4 = *(const float4*)(sb + (kvb + r) * C_ + h * D_ + d4);
            uint4 u = { f2tf32(kv4.x + sv4.x), f2tf32(kv4.y + sv4.y),
                        f2tf32(kv4.z + sv4.z), f2tf32(kv4.w + sv4.w) };
            *(uint4*)&Ks[r * 68 + d4] = u;
        }
        // V transposed [d][kv]
#pragma unroll
        for (int li = 0; li < 4; li++) {
            int f = tid + 256 * li;
            int r = f & 63, d4 = (f >> 6) * 4;
            float4 v4 = *(const float4*)(qkv + (kvb + r) * (3 * C_) + 2 * C_ + h * D_ + d4);
            Vt[(d4 + 0) * 68 + r] = f2tf32(v4.x);
            Vt[(d4 + 1) * 68 + r] = f2tf32(v4.y);
            Vt[(d4 + 2) * 68 + r] = f2tf32(v4.z);
            Vt[(d4 + 3) * 68 + r] = f2tf32(v4.w);
        }
        __syncthreads();

        // ---- S = Q (K+s)^T : warp 16 x 64 ----
        float sc[8][4] = {};
#pragma unroll
        for (int kd = 0; kd < 8; kd++) {
            unsigned bf[8][2];
#pragma unroll
            for (int p = 0; p < 4; p++) {
                int row = p * 16 + (lane & 7) + ((lane & 16) ? 8 : 0);
                int col = kd * 8 + ((lane & 8) ? 4 : 0);
                unsigned tr[4];
                ldm_x4(tr, &Ks[row * 68 + col]);
                bf[p * 2 + 0][0] = tr[0]; bf[p * 2 + 0][1] = tr[1];
                bf[p * 2 + 1][0] = tr[2]; bf[p * 2 + 1][1] = tr[3];
            }
#pragma unroll
            for (int nt = 0; nt < 8; nt++)
                mma_tf32(sc[nt], qf[kd], bf[nt]);
        }

        // ---- online softmax (rows g / g+8 of this warp's 16) ----
        float rmax0 = -1e30f, rmax1 = -1e30f;
#pragma unroll
        for (int nt = 0; nt < 8; nt++) {
            rmax0 = fmaxf(rmax0, fmaxf(sc[nt][0], sc[nt][1]));
            rmax1 = fmaxf(rmax1, fmaxf(sc[nt][2], sc[nt][3]));
        }
#pragma unroll
        for (int off = 1; off <= 2; off <<= 1) {
            rmax0 = fmaxf(rmax0, __shfl_xor_sync(~0u, rmax0, off));
            rmax1 = fmaxf(rmax1, __shfl_xor_sync(~0u, rmax1, off));
        }
        float mn0 = fmaxf(m0v, rmax0), mn1 = fmaxf(m1v, rmax1);
        float cf0 = __expf(m0v - mn0), cf1 = __expf(m1v - mn1);
        m0v = mn0; m1v = mn1;
        float rs0 = 0.f, rs1 = 0.f;
        const int prow = wid * 16 + g;
#pragma unroll
        for (int nt = 0; nt < 8; nt++) {
            float p0 = __expf(sc[nt][0] - mn0);
            float p1 = __expf(sc[nt][1] - mn0);
            float p2 = __expf(sc[nt][2] - mn1);
            float p3 = __expf(sc[nt][3] - mn1);
            rs0 += p0 + p1; rs1 += p2 + p3;
            uint2 u0 = { f2tf32(p0), f2tf32(p1) };
            uint2 u1 = { f2tf32(p2), f2tf32(p3) };
            *(uint2*)&Qs[prow * 68 + nt * 8 + 2 * t] = u0;
            *(uint2*)&Qs[(prow + 8) * 68 + nt * 8 + 2 * t] = u1;
        }
#pragma unroll
        for (int off = 1; off <= 2; off <<= 1) {
            rs0 += __shfl_xor_sync(~0u, rs0, off);
            rs1 += __shfl_xor_sync(~0u, rs1, off);
        }
        l0v = l0v * cf0 + rs0;
        l1v = l1v * cf1 + rs1;
#pragma unroll
        for (int nt = 0; nt < 8; nt++) {
            o[nt][0] *= cf0; o[nt][1] *= cf0;
            o[nt][2] *= cf1; o[nt][3] *= cf1;
        }
        __syncwarp();   // P stores visible to this warp's ldmatrix

        // ---- O += P V ----
#pragma unroll
        for (int kk = 0; kk < 8; kk++) {
            unsigned af[4];
            {
                int row = wid * 16 + (lane & 7) + ((lane & 8) ? 8 : 0);
                int col = kk * 8 + ((lane & 16) ? 4 : 0);
                ldm_x4(af, &Qs[row * 68 + col]);
            }
            unsigned bf[8][2];
#pragma unroll
            for (int p = 0; p < 4; p++) {
                int row = p * 16 + (lane & 7) + ((lane & 16) ? 8 : 0);
                int col = kk * 8 + ((lane & 8) ? 4 : 0);
                unsigned tr[4];
                ldm_x4(tr, &Vt[row * 68 + col]);
                bf[p * 2 + 0][0] = tr[0]; bf[p * 2 + 0][1] = tr[1];
                bf[p * 2 + 1][0] = tr[2]; bf[p * 2 + 1][1] = tr[3];
            }
#pragma unroll
            for (int nt = 0; nt < 8; nt++)
                mma_tf32(o[nt], af, bf[nt]);
        }
    }

    // ---- epilogue: normalize, gate, write ----
    float inv0 = 1.f / l0v, inv1 = 1.f / l1v;
    size_t r0 = qbase + wid * 16 + g;
#pragma unroll
    for (int nt = 0; nt < 8; nt++) {
        int col = h * D_ + nt * 8 + 2 * t;
        float2 g0 = *(const float2*)(gate + r0 * C_ + col);
        float2 g1 = *(const float2*)(gate + (r0 + 8) * C_ + col);
        float2 w0 = { o[nt][0] * inv0 * g0.x, o[nt][1] * inv0 * g0.y };
        float2 w1 = { o[nt][2] * inv1 * g1.x, o[nt][3] * inv1 * g1.y };
        *(float2*)(outp + r0 * C_ + col) = w0;
        *(float2*)(outp + (r0 + 8) * C_ + col) = w1;
    }
}

// ---------------- launch ------------------------------------------------
extern "C" void kernel_launch(void* const* d_in, const int* in_sizes, int n_in,
                              void* d_out, int out_size)
{
    (void)in_sizes; (void)n_in; (void)out_size;
    const float* x    = (const float*)d_in[0];
    const float* e    = (const float*)d_in[1];
    const float* Wqkv = (const float*)d_in[2];
    const float* Ws   = (const float*)d_in[3];
    const float* Wg   = (const float*)d_in[4];
    const float* Wp   = (const float*)d_in[5];
    const float* bp   = (const float*)d_in[6];
    float* out = (float*)d_out;

    float *qkv, *s, *gate, *att;
    unsigned *wqkvT, *wsT, *wgT, *wpT;
    cudaGetSymbolAddress((void**)&qkv,   g_qkv);
    cudaGetSymbolAddress((void**)&s,     g_s);
    cudaGetSymbolAddress((void**)&gate,  g_gate);
    cudaGetSymbolAddress((void**)&att,   g_att);
    cudaGetSymbolAddress((void**)&wqkvT, g_wqkvT);
    cudaGetSymbolAddress((void**)&wsT,   g_wsT);
    cudaGetSymbolAddress((void**)&wgT,   g_wgT);
    cudaGetSymbolAddress((void**)&wpT,   g_wpT);

    static int smem_set = 0;
    if (!smem_set) {
        cudaFuncSetAttribute(flash_tc, cudaFuncAttributeMaxDynamicSharedMemorySize,
                             (128 + 64 + 64) * 68 * 4);
        smem_set = 1;
    }

    dim3 tt(32, 8);
    transpose_cvt<<<dim3(3 * C_ / 32, C_ / 32), tt>>>(Wqkv, wqkvT, C_, 3 * C_);
    transpose_cvt<<<dim3(C_ / 32, C_ / 32), tt>>>(Ws, wsT, C_, C_);
    transpose_cvt<<<dim3(C_ / 32, C_ / 32), tt>>>(Wg, wgT, C_, C_);
    transpose_cvt<<<dim3(C_ / 32, C_ / 32), tt>>>(Wp, wpT, C_, C_);

    // qkv = x @ W_qkv ; gate = x @ W_gate ; s = e @ W_s
    gemm_tf32<0><<<dim3(3 * C_ / 128, M_TOT / 128), 256>>>(x, wqkvT, nullptr, qkv, M_TOT, 3 * C_, C_);
    gemm_tf32<0><<<dim3(C_ / 128, M_TOT / 128), 256>>>(x, wgT, nullptr, gate, M_TOT, C_, C_);
    gemm_tf32<0><<<dim3(C_ / 128, M_TOT / 128), 256>>>(e, wsT, nullptr, s, M_TOT, C_, C_);

    // fused flash attention (k+s fold, scale fold, gate fold)
    flash_tc<<<dim3(N_ / 128, H_, B_), 256, (128 + 64 + 64) * 68 * 4>>>(qkv, s, gate, att);

    // out = att @ W_proj + b_proj
    gemm_tf32<1><<<dim3(C_ / 128, M_TOT / 128), 256>>>(att, wpT, bp, out, M_TOT, C_, C_);
}

// round 8
// speedup vs baseline: 6.5689x; 2.4680x over previous
#include <cuda_runtime.h>
#include <cuda_fp16.h>

#define B_ 2
#define N_ 2048
#define C_ 1024
#define H_ 16
#define D_ 64
#define SCALE_ 0.125f
#define M_TOT (B_ * N_)

// ---------------- scratch (device globals; no allocation) ----------------
__device__ __half g_x_h[(size_t)M_TOT * C_];
__device__ __half g_e_h[(size_t)M_TOT * C_];
__device__ __half g_wqkv_h[(size_t)C_ * 3 * C_];   // [K][N] natural layout
__device__ __half g_ws_h[(size_t)C_ * C_];
__device__ __half g_wg_h[(size_t)C_ * C_];
__device__ __half g_wp_h[(size_t)C_ * C_];
__device__ __half g_qkv_h[(size_t)M_TOT * 3 * C_];
__device__ __half g_s_h[(size_t)M_TOT * C_];
__device__ __half g_gate_h[(size_t)M_TOT * C_];
__device__ __half g_att_h[(size_t)M_TOT * C_];

// ---------------- helpers -------------------------------------------------
__device__ __forceinline__ void ldm_x4(unsigned r[4], const void* p) {
    unsigned a = (unsigned)__cvta_generic_to_shared(p);
    asm volatile("ldmatrix.sync.aligned.m8n8.x4.shared.b16 {%0,%1,%2,%3}, [%4];"
                 : "=r"(r[0]), "=r"(r[1]), "=r"(r[2]), "=r"(r[3]) : "r"(a));
}
__device__ __forceinline__ void ldm_x4t(unsigned r[4], const void* p) {
    unsigned a = (unsigned)__cvta_generic_to_shared(p);
    asm volatile("ldmatrix.sync.aligned.m8n8.x4.trans.shared.b16 {%0,%1,%2,%3}, [%4];"
                 : "=r"(r[0]), "=r"(r[1]), "=r"(r[2]), "=r"(r[3]) : "r"(a));
}
__device__ __forceinline__ void mma_h(float c[4], const unsigned a[4], const unsigned b[2]) {
    asm volatile("mma.sync.aligned.m16n8k16.row.col.f32.f16.f16.f32 "
                 "{%0,%1,%2,%3}, {%4,%5,%6,%7}, {%8,%9}, {%0,%1,%2,%3};"
                 : "+f"(c[0]), "+f"(c[1]), "+f"(c[2]), "+f"(c[3])
                 : "r"(a[0]), "r"(a[1]), "r"(a[2]), "r"(a[3]), "r"(b[0]), "r"(b[1]));
}
__device__ __forceinline__ unsigned h2u(__half2 h) { return *reinterpret_cast<unsigned*>(&h); }
__device__ __forceinline__ unsigned hadd2u(unsigned a, unsigned b) {
    __half2 r = __hadd2(*reinterpret_cast<__half2*>(&a), *reinterpret_cast<__half2*>(&b));
    return h2u(r);
}

// ---------------- fp32 -> fp16 convert ------------------------------------
__global__ void cvt16(const float* __restrict__ in, __half* __restrict__ out, int n) {
    int i = (blockIdx.x * blockDim.x + threadIdx.x) * 8;
    if (i >= n) return;
    float4 a = *(const float4*)(in + i);
    float4 b = *(const float4*)(in + i + 4);
    uint4 u;
    u.x = h2u(__floats2half2_rn(a.x, a.y));
    u.y = h2u(__floats2half2_rn(a.z, a.w));
    u.z = h2u(__floats2half2_rn(b.x, b.y));
    u.w = h2u(__floats2half2_rn(b.z, b.w));
    *(uint4*)(out + i) = u;
}

// ---------------- fp16 GEMM: C = A[M,K] * B[K,N] (+bias) ------------------
// 128x128 tile, BK=32, 256 thr (8 warps 2x4), warp tile 64x32, m16n8k16.
template <int BIAS, int HOUT>
__global__ __launch_bounds__(256) void gemm_h(
    const __half* __restrict__ A, const __half* __restrict__ Bw,
    const float* __restrict__ bias, void* __restrict__ Cout,
    int M, int Nn, int K)
{
    __shared__ __half As[128 * 40];
    __shared__ __half Bs[32 * 136];
    const int tid = threadIdx.x;
    const int wid = tid >> 5, lane = tid & 31;
    const int wm = (wid & 1) * 64, wn = (wid >> 1) * 32;
    const int m_blk = blockIdx.y * 128, n_blk = blockIdx.x * 128;

    const int arow = tid >> 2, acol = (tid & 3) * 8;      // 64 rows/pass
    const int brow = tid >> 4, bcol = (tid & 15) * 8;     // 16 rows/pass

    uint4 pa[2], pb[2];
    auto ld = [&](int kb) {
#pragma unroll
        for (int p = 0; p < 2; p++) {
            pa[p] = *(const uint4*)(A + (size_t)(m_blk + p * 64 + arow) * K + kb * 32 + acol);
            pb[p] = *(const uint4*)(Bw + (size_t)(kb * 32 + p * 16 + brow) * Nn + n_blk + bcol);
        }
    };
    auto st = [&] {
#pragma unroll
        for (int p = 0; p < 2; p++) {
            *(uint4*)&As[(p * 64 + arow) * 40 + acol] = pa[p];
            *(uint4*)&Bs[(p * 16 + brow) * 136 + bcol] = pb[p];
        }
    };

    float acc[4][4][4] = {};
    ld(0); st();
    __syncthreads();

    const int KB = K / 32;
    for (int kb = 0; kb < KB; kb++) {
        if (kb + 1 < KB) ld(kb + 1);
#pragma unroll
        for (int ks = 0; ks < 2; ks++) {
            unsigned af[4][4], bf[4][2];
#pragma unroll
            for (int mt = 0; mt < 4; mt++)
                ldm_x4(af[mt], &As[(wm + mt * 16 + (lane & 15)) * 40 + ks * 16 + (lane >> 4) * 8]);
#pragma unroll
            for (int sl = 0; sl < 2; sl++) {
                unsigned tr[4];
                ldm_x4t(tr, &Bs[(ks * 16 + (lane & 7) + ((lane >> 3) & 1) * 8) * 136
                                + wn + sl * 16 + (lane >> 4) * 8]);
                bf[sl * 2 + 0][0] = tr[0]; bf[sl * 2 + 0][1] = tr[1];
                bf[sl * 2 + 1][0] = tr[2]; bf[sl * 2 + 1][1] = tr[3];
            }
#pragma unroll
            for (int mt = 0; mt < 4; mt++)
#pragma unroll
                for (int nt = 0; nt < 4; nt++)
                    mma_h(acc[mt][nt], af[mt], bf[nt]);
        }
        __syncthreads();
        if (kb + 1 < KB) { st(); __syncthreads(); }
    }

    const int g = lane >> 2, t2 = (lane & 3) * 2;
#pragma unroll
    for (int mt = 0; mt < 4; mt++) {
#pragma unroll
        for (int nt = 0; nt < 4; nt++) {
            int col = n_blk + wn + nt * 8 + t2;
            size_t r0 = (size_t)(m_blk + wm + mt * 16 + g);
            if (HOUT) {
                __half* Ch = (__half*)Cout;
                *(__half2*)(Ch + r0 * Nn + col) = __floats2half2_rn(acc[mt][nt][0], acc[mt][nt][1]);
                *(__half2*)(Ch + (r0 + 8) * Nn + col) = __floats2half2_rn(acc[mt][nt][2], acc[mt][nt][3]);
            } else {
                float* Cf = (float*)Cout;
                float b0 = 0.f, b1 = 0.f;
                if (BIAS) { b0 = bias[col]; b1 = bias[col + 1]; }
                float2 v0 = { acc[mt][nt][0] + b0, acc[mt][nt][1] + b1 };
                float2 v1 = { acc[mt][nt][2] + b0, acc[mt][nt][3] + b1 };
                *(float2*)(Cf + r0 * Nn + col) = v0;
                *(float2*)(Cf + (r0 + 8) * Nn + col) = v1;
            }
        }
    }
}

// ---------------- fp16 tensor-core flash attention -------------------------
// grid (N/128, H, B), 256 thr (8 warps). Warp w owns q-rows 16w..16w+15.
__global__ __launch_bounds__(256) void flash_h(
    const __half* __restrict__ qkv, const __half* __restrict__ sb,
    const __half* __restrict__ gate, __half* __restrict__ outp)
{
    __shared__ __half Qs[128 * 72];   // Q, reused as P (warp-private rows)
    __shared__ __half Ks[64 * 72];    // k+s, row-major [kv][d]
    __shared__ __half Vs[64 * 72];    // v, row-major [kv][d]

    const int qt = blockIdx.x, h = blockIdx.y, b = blockIdx.z;
    const int tid = threadIdx.x;
    const int wid = tid >> 5, lane = tid & 31;
    const int g = lane >> 2, t = lane & 3;
    const size_t qbase = (size_t)(b * N_ + qt * 128);

    // ---- Q -> smem ----
#pragma unroll
    for (int p = 0; p < 4; p++) {
        int r = p * 32 + (tid >> 3), c = (tid & 7) * 8;
        *(uint4*)&Qs[r * 72 + c] =
            *(const uint4*)(qkv + (qbase + r) * (3 * C_) + h * D_ + c);
    }
    __syncthreads();

    // ---- Q fragments -> regs ----
    unsigned qf[4][4];
#pragma unroll
    for (int kd = 0; kd < 4; kd++)
        ldm_x4(qf[kd], &Qs[(wid * 16 + (lane & 15)) * 72 + kd * 16 + (lane >> 4) * 8]);

    float o[8][4] = {};
    float m0v = -1e30f, m1v = -1e30f, l0v = 0.f, l1v = 0.f;

    for (int kt = 0; kt < N_ / 64; kt++) {
        __syncthreads();
        const size_t kvb = (size_t)(b * N_ + kt * 64);

        // ---- K+s and V -> smem ----
#pragma unroll
        for (int p = 0; p < 2; p++) {
            int r = p * 32 + (tid >> 3), c = (tid & 7) * 8;
            uint4 k4 = *(const uint4*)(qkv + (kvb + r) * (3 * C_) + C_ + h * D_ + c);
            uint4 s4 = *(const uint4*)(sb + (kvb + r) * C_ + h * D_ + c);
            uint4 u = { hadd2u(k4.x, s4.x), hadd2u(k4.y, s4.y),
                        hadd2u(k4.z, s4.z), hadd2u(k4.w, s4.w) };
            *(uint4*)&Ks[r * 72 + c] = u;
            *(uint4*)&Vs[r * 72 + c] =
                *(const uint4*)(qkv + (kvb + r) * (3 * C_) + 2 * C_ + h * D_ + c);
        }
        __syncthreads();

        // ---- S = Q (K+s)^T : 16 x 64 per warp ----
        float sc[8][4] = {};
#pragma unroll
        for (int kd = 0; kd < 4; kd++) {
            unsigned bf[8][2];
#pragma unroll
            for (int sp = 0; sp < 4; sp++) {
                unsigned tr[4];
                ldm_x4(tr, &Ks[(sp * 16 + (lane & 7) + (lane >> 4) * 8) * 72
                               + kd * 16 + ((lane >> 3) & 1) * 8]);
                bf[sp * 2 + 0][0] = tr[0]; bf[sp * 2 + 0][1] = tr[1];
                bf[sp * 2 + 1][0] = tr[2]; bf[sp * 2 + 1][1] = tr[3];
            }
#pragma unroll
            for (int nt = 0; nt < 8; nt++)
                mma_h(sc[nt], qf[kd], bf[nt]);
        }
#pragma unroll
        for (int nt = 0; nt < 8; nt++)
#pragma unroll
            for (int i = 0; i < 4; i++) sc[nt][i] *= SCALE_;

        // ---- online softmax (rows g, g+8) ----
        float rmax0 = -1e30f, rmax1 = -1e30f;
#pragma unroll
        for (int nt = 0; nt < 8; nt++) {
            rmax0 = fmaxf(rmax0, fmaxf(sc[nt][0], sc[nt][1]));
            rmax1 = fmaxf(rmax1, fmaxf(sc[nt][2], sc[nt][3]));
        }
#pragma unroll
        for (int off = 1; off <= 2; off <<= 1) {
            rmax0 = fmaxf(rmax0, __shfl_xor_sync(~0u, rmax0, off));
            rmax1 = fmaxf(rmax1, __shfl_xor_sync(~0u, rmax1, off));
        }
        float mn0 = fmaxf(m0v, rmax0), mn1 = fmaxf(m1v, rmax1);
        float cf0 = __expf(m0v - mn0), cf1 = __expf(m1v - mn1);
        m0v = mn0; m1v = mn1;
        float rs0 = 0.f, rs1 = 0.f;
        const int prow = wid * 16 + g;
#pragma unroll
        for (int nt = 0; nt < 8; nt++) {
            float p0 = __expf(sc[nt][0] - mn0);
            float p1 = __expf(sc[nt][1] - mn0);
            float p2 = __expf(sc[nt][2] - mn1);
            float p3 = __expf(sc[nt][3] - mn1);
            rs0 += p0 + p1; rs1 += p2 + p3;
            *(__half2*)&Qs[prow * 72 + nt * 8 + 2 * t] = __floats2half2_rn(p0, p1);
            *(__half2*)&Qs[(prow + 8) * 72 + nt * 8 + 2 * t] = __floats2half2_rn(p2, p3);
        }
#pragma unroll
        for (int off = 1; off <= 2; off <<= 1) {
            rs0 += __shfl_xor_sync(~0u, rs0, off);
            rs1 += __shfl_xor_sync(~0u, rs1, off);
        }
        l0v = l0v * cf0 + rs0;
        l1v = l1v * cf1 + rs1;
#pragma unroll
        for (int nt = 0; nt < 8; nt++) {
            o[nt][0] *= cf0; o[nt][1] *= cf0;
            o[nt][2] *= cf1; o[nt][3] *= cf1;
        }
        __syncwarp();

        // ---- O += P V ----
#pragma unroll
        for (int kk = 0; kk < 4; kk++) {
            unsigned af[4];
            ldm_x4(af, &Qs[(wid * 16 + (lane & 15)) * 72 + kk * 16 + (lane >> 4) * 8]);
            unsigned bf[8][2];
#pragma unroll
            for (int ds = 0; ds < 4; ds++) {
                unsigned tr[4];
                ldm_x4t(tr, &Vs[(kk * 16 + (lane & 7) + ((lane >> 3) & 1) * 8) * 72
                                + ds * 16 + (lane >> 4) * 8]);
                bf[ds * 2 + 0][0] = tr[0]; bf[ds * 2 + 0][1] = tr[1];
                bf[ds * 2 + 1][0] = tr[2]; bf[ds * 2 + 1][1] = tr[3];
            }
#pragma unroll
            for (int nt = 0; nt < 8; nt++)
                mma_h(o[nt], af, bf[nt]);
        }
    }

    // ---- epilogue: normalize, gate, write fp16 att ----
    float inv0 = 1.f / l0v, inv1 = 1.f / l1v;
    size_t r0 = qbase + wid * 16 + g;
#pragma unroll
    for (int nt = 0; nt < 8; nt++) {
        int col = h * D_ + nt * 8 + 2 * t;
        float2 g0 = __half22float2(*(const __half2*)(gate + r0 * C_ + col));
        float2 g1 = __half22float2(*(const __half2*)(gate + (r0 + 8) * C_ + col));
        *(__half2*)(outp + r0 * C_ + col) =
            __floats2half2_rn(o[nt][0] * inv0 * g0.x, o[nt][1] * inv0 * g0.y);
        *(__half2*)(outp + (r0 + 8) * C_ + col) =
            __floats2half2_rn(o[nt][2] * inv1 * g1.x, o[nt][3] * inv1 * g1.y);
    }
}

// ---------------- launch ------------------------------------------------
extern "C" void kernel_launch(void* const* d_in, const int* in_sizes, int n_in,
                              void* d_out, int out_size)
{
    (void)in_sizes; (void)n_in; (void)out_size;
    const float* x    = (const float*)d_in[0];
    const float* e    = (const float*)d_in[1];
    const float* Wqkv = (const float*)d_in[2];
    const float* Ws   = (const float*)d_in[3];
    const float* Wg   = (const float*)d_in[4];
    const float* Wp   = (const float*)d_in[5];
    const float* bp   = (const float*)d_in[6];
    float* out = (float*)d_out;

    __half *xh, *eh, *wqkvh, *wsh, *wgh, *wph, *qkvh, *sh, *gateh, *atth;
    cudaGetSymbolAddress((void**)&xh,    g_x_h);
    cudaGetSymbolAddress((void**)&eh,    g_e_h);
    cudaGetSymbolAddress((void**)&wqkvh, g_wqkv_h);
    cudaGetSymbolAddress((void**)&wsh,   g_ws_h);
    cudaGetSymbolAddress((void**)&wgh,   g_wg_h);
    cudaGetSymbolAddress((void**)&wph,   g_wp_h);
    cudaGetSymbolAddress((void**)&qkvh,  g_qkv_h);
    cudaGetSymbolAddress((void**)&sh,    g_s_h);
    cudaGetSymbolAddress((void**)&gateh, g_gate_h);
    cudaGetSymbolAddress((void**)&atth,  g_att_h);

    const int nxe = M_TOT * C_;            // 4M
    const int nw1 = C_ * C_;               // 1M
    cvt16<<<nxe / 2048, 256>>>(x, xh, nxe);
    cvt16<<<nxe / 2048, 256>>>(e, eh, nxe);
    cvt16<<<3 * nw1 / 2048, 256>>>(Wqkv, wqkvh, 3 * nw1);
    cvt16<<<nw1 / 2048, 256>>>(Ws, wsh, nw1);
    cvt16<<<nw1 / 2048, 256>>>(Wg, wgh, nw1);
    cvt16<<<nw1 / 2048, 256>>>(Wp, wph, nw1);

    gemm_h<0, 1><<<dim3(3 * C_ / 128, M_TOT / 128), 256>>>(xh, wqkvh, nullptr, qkvh, M_TOT, 3 * C_, C_);
    gemm_h<0, 1><<<dim3(C_ / 128, M_TOT / 128), 256>>>(xh, wgh, nullptr, gateh, M_TOT, C_, C_);
    gemm_h<0, 1><<<dim3(C_ / 128, M_TOT / 128), 256>>>(eh, wsh, nullptr, sh, M_TOT, C_, C_);

    flash_h<<<dim3(N_ / 128, H_, B_), 256>>>(qkvh, sh, gateh, atth);

    gemm_h<1, 0><<<dim3(C_ / 128, M_TOT / 128), 256>>>(atth, wph, bp, out, M_TOT, C_, C_);
}

// round 9
// speedup vs baseline: 7.0720x; 1.0766x over previous
#include <cuda_runtime.h>
#include <cuda_fp16.h>

#define B_ 2
#define N_ 2048
#define C_ 1024
#define H_ 16
#define D_ 64
#define SCALE_ 0.125f
#define M_TOT (B_ * N_)
#define C4_ (4 * C_)

// ---------------- scratch (device globals; no allocation) ----------------
__device__ __half g_x_h[(size_t)M_TOT * C_];
__device__ __half g_e_h[(size_t)M_TOT * C_];
__device__ __half g_wqkvg_h[(size_t)C_ * C4_];     // [K][4C] = [Wqkv | Wgate]
__device__ __half g_ws_h[(size_t)C_ * C_];
__device__ __half g_wp_h[(size_t)C_ * C_];
__device__ __half g_qkvg_h[(size_t)M_TOT * C4_];   // [M][4C] = q|k|v|gate
__device__ __half g_s_h[(size_t)M_TOT * C_];
__device__ __half g_att_h[(size_t)M_TOT * C_];

// ---------------- helpers -------------------------------------------------
__device__ __forceinline__ void ldm_x4(unsigned r[4], const void* p) {
    unsigned a = (unsigned)__cvta_generic_to_shared(p);
    asm volatile("ldmatrix.sync.aligned.m8n8.x4.shared.b16 {%0,%1,%2,%3}, [%4];"
                 : "=r"(r[0]), "=r"(r[1]), "=r"(r[2]), "=r"(r[3]) : "r"(a));
}
__device__ __forceinline__ void ldm_x4t(unsigned r[4], const void* p) {
    unsigned a = (unsigned)__cvta_generic_to_shared(p);
    asm volatile("ldmatrix.sync.aligned.m8n8.x4.trans.shared.b16 {%0,%1,%2,%3}, [%4];"
                 : "=r"(r[0]), "=r"(r[1]), "=r"(r[2]), "=r"(r[3]) : "r"(a));
}
__device__ __forceinline__ void mma_h(float c[4], const unsigned a[4], const unsigned b[2]) {
    asm volatile("mma.sync.aligned.m16n8k16.row.col.f32.f16.f16.f32 "
                 "{%0,%1,%2,%3}, {%4,%5,%6,%7}, {%8,%9}, {%0,%1,%2,%3};"
                 : "+f"(c[0]), "+f"(c[1]), "+f"(c[2]), "+f"(c[3])
                 : "r"(a[0]), "r"(a[1]), "r"(a[2]), "r"(a[3]), "r"(b[0]), "r"(b[1]));
}
__device__ __forceinline__ unsigned h2u(__half2 h) { return *reinterpret_cast<unsigned*>(&h); }
__device__ __forceinline__ unsigned hadd2u(unsigned a, unsigned b) {
    __half2 r = __hadd2(*reinterpret_cast<__half2*>(&a), *reinterpret_cast<__half2*>(&b));
    return h2u(r);
}

// ---------------- fp32 -> fp16 converts ------------------------------------
__global__ void cvt16(const float* __restrict__ in, __half* __restrict__ out, int n) {
    int i = (blockIdx.x * blockDim.x + threadIdx.x) * 4;
    if (i >= n) return;
    float4 a = *(const float4*)(in + i);
    uint2 u = { h2u(__floats2half2_rn(a.x, a.y)), h2u(__floats2half2_rn(a.z, a.w)) };
    *(uint2*)(out + i) = u;
}
// strided variant: scatter [K][ncol] source into out rows of stride ostride at col ooff
__global__ void cvt16s(const float* __restrict__ in, __half* __restrict__ out,
                       int ncol, int ostride, int ooff, int n) {
    int i = (blockIdx.x * blockDim.x + threadIdx.x) * 4;
    if (i >= n) return;
    int row = i / ncol, col = i - row * ncol;
    float4 a = *(const float4*)(in + i);
    uint2 u = { h2u(__floats2half2_rn(a.x, a.y)), h2u(__floats2half2_rn(a.z, a.w)) };
    *(uint2*)(out + (size_t)row * ostride + ooff + col) = u;
}

// ---------------- fp16 GEMM: C = A[M,K] * B[K,N] (+bias), double-buffered --
// 128x128 tile, BK=32, 256 thr (8 warps 2x4), warp tile 64x32, m16n8k16.
template <int BIAS, int HOUT>
__global__ __launch_bounds__(256) void gemm_h(
    const __half* __restrict__ A, const __half* __restrict__ Bw,
    const float* __restrict__ bias, void* __restrict__ Cout,
    int M, int Nn, int K)
{
    __shared__ __half As[2][128 * 40];
    __shared__ __half Bs[2][32 * 136];
    const int tid = threadIdx.x;
    const int wid = tid >> 5, lane = tid & 31;
    const int wm = (wid & 1) * 64, wn = (wid >> 1) * 32;
    const int m_blk = blockIdx.y * 128, n_blk = blockIdx.x * 128;

    const int arow = tid >> 2, acol = (tid & 3) * 8;
    const int brow = tid >> 4, bcol = (tid & 15) * 8;

    uint4 pa[2], pb[2];
    auto ld = [&](int kb) {
#pragma unroll
        for (int p = 0; p < 2; p++) {
            pa[p] = *(const uint4*)(A + (size_t)(m_blk + p * 64 + arow) * K + kb * 32 + acol);
            pb[p] = *(const uint4*)(Bw + (size_t)(kb * 32 + p * 16 + brow) * Nn + n_blk + bcol);
        }
    };
    auto st = [&](int s) {
#pragma unroll
        for (int p = 0; p < 2; p++) {
            *(uint4*)&As[s][(p * 64 + arow) * 40 + acol] = pa[p];
            *(uint4*)&Bs[s][(p * 16 + brow) * 136 + bcol] = pb[p];
        }
    };

    float acc[4][4][4] = {};
    ld(0); st(0);
    __syncthreads();

    const int KB = K / 32;
    for (int kb = 0; kb < KB; kb++) {
        if (kb + 1 < KB) ld(kb + 1);
        const int cs = kb & 1;
#pragma unroll
        for (int ks = 0; ks < 2; ks++) {
            unsigned af[4][4], bf[4][2];
#pragma unroll
            for (int mt = 0; mt < 4; mt++)
                ldm_x4(af[mt], &As[cs][(wm + mt * 16 + (lane & 15)) * 40 + ks * 16 + (lane >> 4) * 8]);
#pragma unroll
            for (int sl = 0; sl < 2; sl++) {
                unsigned tr[4];
                ldm_x4t(tr, &Bs[cs][(ks * 16 + (lane & 7) + ((lane >> 3) & 1) * 8) * 136
                                    + wn + sl * 16 + (lane >> 4) * 8]);
                bf[sl * 2 + 0][0] = tr[0]; bf[sl * 2 + 0][1] = tr[1];
                bf[sl * 2 + 1][0] = tr[2]; bf[sl * 2 + 1][1] = tr[3];
            }
#pragma unroll
            for (int mt = 0; mt < 4; mt++)
#pragma unroll
                for (int nt = 0; nt < 4; nt++)
                    mma_h(acc[mt][nt], af[mt], bf[nt]);
        }
        if (kb + 1 < KB) st((kb + 1) & 1);
        __syncthreads();
    }

    const int g = lane >> 2, t2 = (lane & 3) * 2;
#pragma unroll
    for (int mt = 0; mt < 4; mt++) {
#pragma unroll
        for (int nt = 0; nt < 4; nt++) {
            int col = n_blk + wn + nt * 8 + t2;
            size_t r0 = (size_t)(m_blk + wm + mt * 16 + g);
            if (HOUT) {
                __half* Ch = (__half*)Cout;
                *(__half2*)(Ch + r0 * Nn + col) = __floats2half2_rn(acc[mt][nt][0], acc[mt][nt][1]);
                *(__half2*)(Ch + (r0 + 8) * Nn + col) = __floats2half2_rn(acc[mt][nt][2], acc[mt][nt][3]);
            } else {
                float* Cf = (float*)Cout;
                float b0 = 0.f, b1 = 0.f;
                if (BIAS) { b0 = bias[col]; b1 = bias[col + 1]; }
                float2 v0 = { acc[mt][nt][0] + b0, acc[mt][nt][1] + b1 };
                float2 v1 = { acc[mt][nt][2] + b0, acc[mt][nt][3] + b1 };
                *(float2*)(Cf + r0 * Nn + col) = v0;
                *(float2*)(Cf + (r0 + 8) * Nn + col) = v1;
            }
        }
    }
}

// ---------------- fp16 flash attention, double-buffered KV -----------------
// grid (N/128, H, B), 256 thr (8 warps). Warp w owns q-rows 16w..16w+15.
// qkvg rows have stride 4C: [q | k | v | gate].
__global__ __launch_bounds__(256) void flash_h(
    const __half* __restrict__ qkvg, const __half* __restrict__ sb,
    __half* __restrict__ outp)
{
    extern __shared__ __half smh[];
    __half* Qs = smh;                        // [128][72], reused as P
    __half* Ks = smh + 128 * 72;             // 2 x [64][72]
    __half* Vs = smh + 128 * 72 + 2 * 64 * 72;

    const int qt = blockIdx.x, h = blockIdx.y, b = blockIdx.z;
    const int tid = threadIdx.x;
    const int wid = tid >> 5, lane = tid & 31;
    const int g = lane >> 2, t = lane & 3;
    const size_t qbase = (size_t)(b * N_ + qt * 128);

    const int lr = tid >> 3, lc = (tid & 7) * 8;

    uint4 rk[2], rs[2], rv[2];
    auto ldkv = [&](int kt) {
        const size_t kvb = (size_t)(b * N_ + kt * 64);
#pragma unroll
        for (int p = 0; p < 2; p++) {
            int r = p * 32 + lr;
            rk[p] = *(const uint4*)(qkvg + (kvb + r) * C4_ + C_ + h * D_ + lc);
            rs[p] = *(const uint4*)(sb + (kvb + r) * C_ + h * D_ + lc);
            rv[p] = *(const uint4*)(qkvg + (kvb + r) * C4_ + 2 * C_ + h * D_ + lc);
        }
    };
    auto stkv = [&](int s) {
#pragma unroll
        for (int p = 0; p < 2; p++) {
            int r = p * 32 + lr;
            uint4 u = { hadd2u(rk[p].x, rs[p].x), hadd2u(rk[p].y, rs[p].y),
                        hadd2u(rk[p].z, rs[p].z), hadd2u(rk[p].w, rs[p].w) };
            *(uint4*)&Ks[s * (64 * 72) + r * 72 + lc] = u;
            *(uint4*)&Vs[s * (64 * 72) + r * 72 + lc] = rv[p];
        }
    };

    // ---- prefetch KV tile 0; load Q -> smem ----
    ldkv(0);
#pragma unroll
    for (int p = 0; p < 4; p++) {
        int r = p * 32 + lr;
        *(uint4*)&Qs[r * 72 + lc] = *(const uint4*)(qkvg + (qbase + r) * C4_ + h * D_ + lc);
    }
    __syncthreads();

    unsigned qf[4][4];
#pragma unroll
    for (int kd = 0; kd < 4; kd++)
        ldm_x4(qf[kd], &Qs[(wid * 16 + (lane & 15)) * 72 + kd * 16 + (lane >> 4) * 8]);
    stkv(0);
    __syncthreads();

    float o[8][4] = {};
    float m0v = -1e30f, m1v = -1e30f, l0v = 0.f, l1v = 0.f;

    for (int kt = 0; kt < N_ / 64; kt++) {
        const int cs = kt & 1;
        const __half* Kc = Ks + cs * (64 * 72);
        const __half* Vc = Vs + cs * (64 * 72);

        // ---- S = Q (K+s)^T : 16 x 64 per warp ----
        float sc[8][4] = {};
#pragma unroll
        for (int kd = 0; kd < 4; kd++) {
            unsigned bf[8][2];
#pragma unroll
            for (int sp = 0; sp < 4; sp++) {
                unsigned tr[4];
                ldm_x4(tr, &Kc[(sp * 16 + (lane & 7) + (lane >> 4) * 8) * 72
                               + kd * 16 + ((lane >> 3) & 1) * 8]);
                bf[sp * 2 + 0][0] = tr[0]; bf[sp * 2 + 0][1] = tr[1];
                bf[sp * 2 + 1][0] = tr[2]; bf[sp * 2 + 1][1] = tr[3];
            }
#pragma unroll
            for (int nt = 0; nt < 8; nt++)
                mma_h(sc[nt], qf[kd], bf[nt]);
        }
#pragma unroll
        for (int nt = 0; nt < 8; nt++)
#pragma unroll
            for (int i = 0; i < 4; i++) sc[nt][i] *= SCALE_;

        // ---- online softmax (rows g, g+8) ----
        float rmax0 = -1e30f, rmax1 = -1e30f;
#pragma unroll
        for (int nt = 0; nt < 8; nt++) {
            rmax0 = fmaxf(rmax0, fmaxf(sc[nt][0], sc[nt][1]));
            rmax1 = fmaxf(rmax1, fmaxf(sc[nt][2], sc[nt][3]));
        }
#pragma unroll
        for (int off = 1; off <= 2; off <<= 1) {
            rmax0 = fmaxf(rmax0, __shfl_xor_sync(~0u, rmax0, off));
            rmax1 = fmaxf(rmax1, __shfl_xor_sync(~0u, rmax1, off));
        }
        float mn0 = fmaxf(m0v, rmax0), mn1 = fmaxf(m1v, rmax1);
        float cf0 = __expf(m0v - mn0), cf1 = __expf(m1v - mn1);
        m0v = mn0; m1v = mn1;
        float rs0 = 0.f, rs1 = 0.f;
        const int prow = wid * 16 + g;
#pragma unroll
        for (int nt = 0; nt < 8; nt++) {
            float p0 = __expf(sc[nt][0] - mn0);
            float p1 = __expf(sc[nt][1] - mn0);
            float p2 = __expf(sc[nt][2] - mn1);
            float p3 = __expf(sc[nt][3] - mn1);
            rs0 += p0 + p1; rs1 += p2 + p3;
            *(__half2*)&Qs[prow * 72 + nt * 8 + 2 * t] = __floats2half2_rn(p0, p1);
            *(__half2*)&Qs[(prow + 8) * 72 + nt * 8 + 2 * t] = __floats2half2_rn(p2, p3);
        }
#pragma unroll
        for (int off = 1; off <= 2; off <<= 1) {
            rs0 += __shfl_xor_sync(~0u, rs0, off);
            rs1 += __shfl_xor_sync(~0u, rs1, off);
        }
        l0v = l0v * cf0 + rs0;
        l1v = l1v * cf1 + rs1;
#pragma unroll
        for (int nt = 0; nt < 8; nt++) {
            o[nt][0] *= cf0; o[nt][1] *= cf0;
            o[nt][2] *= cf1; o[nt][3] *= cf1;
        }
        __syncwarp();

        // ---- prefetch next KV (sc regs now dead; hidden under PV mma) ----
        if (kt + 1 < N_ / 64) ldkv(kt + 1);

        // ---- O += P V ----
#pragma unroll
        for (int kk = 0; kk < 4; kk++) {
            unsigned af[4];
            ldm_x4(af, &Qs[(wid * 16 + (lane & 15)) * 72 + kk * 16 + (lane >> 4) * 8]);
            unsigned bf[8][2];
#pragma unroll
            for (int ds = 0; ds < 4; ds++) {
                unsigned tr[4];
                ldm_x4t(tr, &Vc[(kk * 16 + (lane & 7) + ((lane >> 3) & 1) * 8) * 72
                                + ds * 16 + (lane >> 4) * 8]);
                bf[ds * 2 + 0][0] = tr[0]; bf[ds * 2 + 0][1] = tr[1];
                bf[ds * 2 + 1][0] = tr[2]; bf[ds * 2 + 1][1] = tr[3];
            }
#pragma unroll
            for (int nt = 0; nt < 8; nt++)
                mma_h(o[nt], af, bf[nt]);
        }

        if (kt + 1 < N_ / 64) stkv((kt + 1) & 1);
        __syncthreads();
    }

    // ---- epilogue: normalize, gate (from qkvg col 3C), write fp16 att ----
    float inv0 = 1.f / l0v, inv1 = 1.f / l1v;
    size_t r0 = qbase + wid * 16 + g;
#pragma unroll
    for (int nt = 0; nt < 8; nt++) {
        int col = h * D_ + nt * 8 + 2 * t;
        float2 g0 = __half22float2(*(const __half2*)(qkvg + r0 * C4_ + 3 * C_ + col));
        float2 g1 = __half22float2(*(const __half2*)(qkvg + (r0 + 8) * C4_ + 3 * C_ + col));
        *(__half2*)(outp + r0 * C_ + col) =
            __floats2half2_rn(o[nt][0] * inv0 * g0.x, o[nt][1] * inv0 * g0.y);
        *(__half2*)(outp + (r0 + 8) * C_ + col) =
            __floats2half2_rn(o[nt][2] * inv1 * g1.x, o[nt][3] * inv1 * g1.y);
    }
}

// ---------------- launch ------------------------------------------------
extern "C" void kernel_launch(void* const* d_in, const int* in_sizes, int n_in,
                              void* d_out, int out_size)
{
    (void)in_sizes; (void)n_in; (void)out_size;
    const float* x    = (const float*)d_in[0];
    const float* e    = (const float*)d_in[1];
    const float* Wqkv = (const float*)d_in[2];
    const float* Ws   = (const float*)d_in[3];
    const float* Wg   = (const float*)d_in[4];
    const float* Wp   = (const float*)d_in[5];
    const float* bp   = (const float*)d_in[6];
    float* out = (float*)d_out;

    __half *xh, *eh, *wqkvgh, *wsh, *wph, *qkvgh, *sh, *atth;
    cudaGetSymbolAddress((void**)&xh,     g_x_h);
    cudaGetSymbolAddress((void**)&eh,     g_e_h);
    cudaGetSymbolAddress((void**)&wqkvgh, g_wqkvg_h);
    cudaGetSymbolAddress((void**)&wsh,    g_ws_h);
    cudaGetSymbolAddress((void**)&wph,    g_wp_h);
    cudaGetSymbolAddress((void**)&qkvgh,  g_qkvg_h);
    cudaGetSymbolAddress((void**)&sh,     g_s_h);
    cudaGetSymbolAddress((void**)&atth,   g_att_h);

    static int smem_set = 0;
    const int flash_smem = (128 + 2 * 64 + 2 * 64) * 72 * 2;
    if (!smem_set) {
        cudaFuncSetAttribute(flash_h, cudaFuncAttributeMaxDynamicSharedMemorySize, flash_smem);
        smem_set = 1;
    }

    const int nxe = M_TOT * C_;   // 4M
    const int nw1 = C_ * C_;      // 1M
    cvt16<<<nxe / 1024, 256>>>(x, xh, nxe);
    cvt16<<<nxe / 1024, 256>>>(e, eh, nxe);
    cvt16s<<<3 * nw1 / 1024, 256>>>(Wqkv, wqkvgh, 3 * C_, C4_, 0, 3 * nw1);
    cvt16s<<<nw1 / 1024, 256>>>(Wg, wqkvgh, C_, C4_, 3 * C_, nw1);
    cvt16<<<nw1 / 1024, 256>>>(Ws, wsh, nw1);
    cvt16<<<nw1 / 1024, 256>>>(Wp, wph, nw1);

    // qkvg = x @ [Wqkv | Wgate]  (N = 4C)
    gemm_h<0, 1><<<dim3(C4_ / 128, M_TOT / 128), 256>>>(xh, wqkvgh, nullptr, qkvgh, M_TOT, C4_, C_);
    // s = e @ W_s
    gemm_h<0, 1><<<dim3(C_ / 128, M_TOT / 128), 256>>>(eh, wsh, nullptr, sh, M_TOT, C_, C_);

    // fused flash attention (k+s fold, scale fold, gate fold)
    flash_h<<<dim3(N_ / 128, H_, B_), 256, flash_smem>>>(qkvgh, sh, atth);

    // out = att @ W_proj + b_proj
    gemm_h<1, 0><<<dim3(C_ / 128, M_TOT / 128), 256>>>(atth, wph, bp, out, M_TOT, C_, C_);
}

// round 10
// speedup vs baseline: 7.1941x; 1.0173x over previous
#include <cuda_runtime.h>
#include <cuda_fp16.h>

#define B_ 2
#define N_ 2048
#define C_ 1024
#define H_ 16
#define D_ 64
#define SCALE_ 0.125f
#define M_TOT (B_ * N_)
#define C4_ (4 * C_)

// ---------------- scratch (device globals; no allocation) ----------------
__device__ __half g_x_h[(size_t)M_TOT * C_];
__device__ __half g_e_h[(size_t)M_TOT * C_];
__device__ __half g_wqkvg_h[(size_t)C_ * C4_];     // [K][4C] = [Wqkv | Wgate]
__device__ __half g_ws_h[(size_t)C_ * C_];
__device__ __half g_wp_h[(size_t)C_ * C_];
__device__ __half g_qkvg_h[(size_t)M_TOT * C4_];   // [M][4C] = q|k|v|gate
__device__ __half g_s_h[(size_t)M_TOT * C_];
__device__ __half g_att_h[(size_t)M_TOT * C_];

// ---------------- helpers -------------------------------------------------
__device__ __forceinline__ void ldm_x4(unsigned r[4], const void* p) {
    unsigned a = (unsigned)__cvta_generic_to_shared(p);
    asm volatile("ldmatrix.sync.aligned.m8n8.x4.shared.b16 {%0,%1,%2,%3}, [%4];"
                 : "=r"(r[0]), "=r"(r[1]), "=r"(r[2]), "=r"(r[3]) : "r"(a));
}
__device__ __forceinline__ void ldm_x4t(unsigned r[4], const void* p) {
    unsigned a = (unsigned)__cvta_generic_to_shared(p);
    asm volatile("ldmatrix.sync.aligned.m8n8.x4.trans.shared.b16 {%0,%1,%2,%3}, [%4];"
                 : "=r"(r[0]), "=r"(r[1]), "=r"(r[2]), "=r"(r[3]) : "r"(a));
}
__device__ __forceinline__ void mma_h(float c[4], const unsigned a[4], const unsigned b[2]) {
    asm volatile("mma.sync.aligned.m16n8k16.row.col.f32.f16.f16.f32 "
                 "{%0,%1,%2,%3}, {%4,%5,%6,%7}, {%8,%9}, {%0,%1,%2,%3};"
                 : "+f"(c[0]), "+f"(c[1]), "+f"(c[2]), "+f"(c[3])
                 : "r"(a[0]), "r"(a[1]), "r"(a[2]), "r"(a[3]), "r"(b[0]), "r"(b[1]));
}
__device__ __forceinline__ unsigned h2u(__half2 h) { return *reinterpret_cast<unsigned*>(&h); }
__device__ __forceinline__ unsigned hadd2u(unsigned a, unsigned b) {
    __half2 r = __hadd2(*reinterpret_cast<__half2*>(&a), *reinterpret_cast<__half2*>(&b));
    return h2u(r);
}
__device__ __forceinline__ unsigned hmul2u(unsigned a, __half2 s) {
    __half2 r = __hmul2(*reinterpret_cast<__half2*>(&a), s);
    return h2u(r);
}

// ---------------- fused fp32 -> fp16 convert (all tensors, one launch) -----
__device__ __forceinline__ void cv4(const float* __restrict__ in,
                                    __half* __restrict__ out, int i) {
    float4 a = *(const float4*)(in + i);
    uint2 u = { h2u(__floats2half2_rn(a.x, a.y)), h2u(__floats2half2_rn(a.z, a.w)) };
    *(uint2*)(out + i) = u;
}
__device__ __forceinline__ void cv4s(const float* __restrict__ in,
                                     __half* __restrict__ out, int i,
                                     int ncol, int ooff) {
    int row = i / ncol, col = i - row * ncol;
    float4 a = *(const float4*)(in + i);
    uint2 u = { h2u(__floats2half2_rn(a.x, a.y)), h2u(__floats2half2_rn(a.z, a.w)) };
    *(uint2*)(out + (size_t)row * C4_ + ooff + col) = u;
}
// block ranges: [0,4096) x, [4096,8192) e, [8192,11264) Wqkv->qkvg,
// [11264,12288) Wg->qkvg, [12288,13312) Ws, [13312,14336) Wp
__global__ void cvt_all(const float* __restrict__ x, const float* __restrict__ e,
                        const float* __restrict__ wqkv, const float* __restrict__ wg,
                        const float* __restrict__ ws, const float* __restrict__ wp,
                        __half* __restrict__ xh, __half* __restrict__ eh,
                        __half* __restrict__ wqkvgh, __half* __restrict__ wsh,
                        __half* __restrict__ wph)
{
    int blk = blockIdx.x;
    int t4 = threadIdx.x * 4;
    if (blk < 4096)            cv4(x, xh, blk * 1024 + t4);
    else if (blk < 8192)       cv4(e, eh, (blk - 4096) * 1024 + t4);
    else if (blk < 11264)      cv4s(wqkv, wqkvgh, (blk - 8192) * 1024 + t4, 3 * C_, 0);
    else if (blk < 12288)      cv4s(wg, wqkvgh, (blk - 11264) * 1024 + t4, C_, 3 * C_);
    else if (blk < 13312)      cv4(ws, wsh, (blk - 12288) * 1024 + t4);
    else                       cv4(wp, wph, (blk - 13312) * 1024 + t4);
}

// ---------------- fp16 GEMM core (double-buffered, m16n8k16) ---------------
// 128x128 tile, BK=32, 256 thr (8 warps 2x4), warp tile 64x32.
template <int BIAS, int HOUT>
__device__ __forceinline__ void gemm_body(
    const __half* __restrict__ A, const __half* __restrict__ Bw,
    const float* __restrict__ bias, void* __restrict__ Cout,
    int Nn, int K, int m_blk, int n_blk,
    __half (*As)[128 * 40], __half (*Bs)[32 * 136])
{
    const int tid = threadIdx.x;
    const int wid = tid >> 5, lane = tid & 31;
    const int wm = (wid & 1) * 64, wn = (wid >> 1) * 32;

    const int arow = tid >> 2, acol = (tid & 3) * 8;
    const int brow = tid >> 4, bcol = (tid & 15) * 8;

    uint4 pa[2], pb[2];
    auto ld = [&](int kb) {
#pragma unroll
        for (int p = 0; p < 2; p++) {
            pa[p] = *(const uint4*)(A + (size_t)(m_blk + p * 64 + arow) * K + kb * 32 + acol);
            pb[p] = *(const uint4*)(Bw + (size_t)(kb * 32 + p * 16 + brow) * Nn + n_blk + bcol);
        }
    };
    auto st = [&](int s) {
#pragma unroll
        for (int p = 0; p < 2; p++) {
            *(uint4*)&As[s][(p * 64 + arow) * 40 + acol] = pa[p];
            *(uint4*)&Bs[s][(p * 16 + brow) * 136 + bcol] = pb[p];
        }
    };

    float acc[4][4][4] = {};
    ld(0); st(0);
    __syncthreads();

    const int KB = K / 32;
    for (int kb = 0; kb < KB; kb++) {
        if (kb + 1 < KB) ld(kb + 1);
        const int cs = kb & 1;
#pragma unroll
        for (int ks = 0; ks < 2; ks++) {
            unsigned af[4][4], bf[4][2];
#pragma unroll
            for (int mt = 0; mt < 4; mt++)
                ldm_x4(af[mt], &As[cs][(wm + mt * 16 + (lane & 15)) * 40 + ks * 16 + (lane >> 4) * 8]);
#pragma unroll
            for (int sl = 0; sl < 2; sl++) {
                unsigned tr[4];
                ldm_x4t(tr, &Bs[cs][(ks * 16 + (lane & 7) + ((lane >> 3) & 1) * 8) * 136
                                    + wn + sl * 16 + (lane >> 4) * 8]);
                bf[sl * 2 + 0][0] = tr[0]; bf[sl * 2 + 0][1] = tr[1];
                bf[sl * 2 + 1][0] = tr[2]; bf[sl * 2 + 1][1] = tr[3];
            }
#pragma unroll
            for (int mt = 0; mt < 4; mt++)
#pragma unroll
                for (int nt = 0; nt < 4; nt++)
                    mma_h(acc[mt][nt], af[mt], bf[nt]);
        }
        if (kb + 1 < KB) st((kb + 1) & 1);
        __syncthreads();
    }

    const int g = lane >> 2, t2 = (lane & 3) * 2;
#pragma unroll
    for (int mt = 0; mt < 4; mt++) {
#pragma unroll
        for (int nt = 0; nt < 4; nt++) {
            int col = n_blk + wn + nt * 8 + t2;
            size_t r0 = (size_t)(m_blk + wm + mt * 16 + g);
            if (HOUT) {
                __half* Ch = (__half*)Cout;
                *(__half2*)(Ch + r0 * Nn + col) = __floats2half2_rn(acc[mt][nt][0], acc[mt][nt][1]);
                *(__half2*)(Ch + (r0 + 8) * Nn + col) = __floats2half2_rn(acc[mt][nt][2], acc[mt][nt][3]);
            } else {
                float* Cf = (float*)Cout;
                float b0 = 0.f, b1 = 0.f;
                if (BIAS) { b0 = bias[col]; b1 = bias[col + 1]; }
                float2 v0 = { acc[mt][nt][0] + b0, acc[mt][nt][1] + b1 };
                float2 v1 = { acc[mt][nt][2] + b0, acc[mt][nt][3] + b1 };
                *(float2*)(Cf + r0 * Nn + col) = v0;
                *(float2*)(Cf + (r0 + 8) * Nn + col) = v1;
            }
        }
    }
}

// fused launch: bx<32 -> qkvg = x@[Wqkv|Wg] (N=4C); bx>=32 -> s = e@Ws (N=C)
__global__ __launch_bounds__(256) void gemm_fused(
    const __half* __restrict__ xh, const __half* __restrict__ wqkvg,
    __half* __restrict__ qkvg,
    const __half* __restrict__ eh, const __half* __restrict__ ws,
    __half* __restrict__ sh)
{
    __shared__ __half As[2][128 * 40];
    __shared__ __half Bs[2][32 * 136];
    const int bx = blockIdx.x;
    const int m_blk = blockIdx.y * 128;
    if (bx < 32)
        gemm_body<0, 1>(xh, wqkvg, nullptr, qkvg, C4_, C_, m_blk, bx * 128, As, Bs);
    else
        gemm_body<0, 1>(eh, ws, nullptr, sh, C_, C_, m_blk, (bx - 32) * 128, As, Bs);
}

// proj: out = att @ W_proj + bias (fp32 out)
__global__ __launch_bounds__(256) void gemm_proj(
    const __half* __restrict__ atth, const __half* __restrict__ wp,
    const float* __restrict__ bias, float* __restrict__ out)
{
    __shared__ __half As[2][128 * 40];
    __shared__ __half Bs[2][32 * 136];
    gemm_body<1, 0>(atth, wp, bias, out, C_, C_, blockIdx.y * 128, blockIdx.x * 128, As, Bs);
}

// ---------------- fp16 flash attention: P in registers ---------------------
// grid (N/128, H, B), 256 thr (8 warps). Warp w owns q-rows 16w..16w+15.
// qkvg rows have stride 4C: [q | k | v | gate]. Scale folded into Q load.
__global__ __launch_bounds__(256) void flash_h(
    const __half* __restrict__ qkvg, const __half* __restrict__ sb,
    __half* __restrict__ outp)
{
    extern __shared__ __half smh[];
    __half* Qs = smh;                        // [128][72] (staging only)
    __half* Ks = smh + 128 * 72;             // 2 x [64][72]
    __half* Vs = smh + 128 * 72 + 2 * 64 * 72;

    const int qt = blockIdx.x, h = blockIdx.y, b = blockIdx.z;
    const int tid = threadIdx.x;
    const int wid = tid >> 5, lane = tid & 31;
    const size_t qbase = (size_t)(b * N_ + qt * 128);

    const int lr = tid >> 3, lc = (tid & 7) * 8;

    uint4 rk[2], rs[2], rv[2];
    auto ldkv = [&](int kt) {
        const size_t kvb = (size_t)(b * N_ + kt * 64);
#pragma unroll
        for (int p = 0; p < 2; p++) {
            int r = p * 32 + lr;
            rk[p] = *(const uint4*)(qkvg + (kvb + r) * C4_ + C_ + h * D_ + lc);
            rs[p] = *(const uint4*)(sb + (kvb + r) * C_ + h * D_ + lc);
            rv[p] = *(const uint4*)(qkvg + (kvb + r) * C4_ + 2 * C_ + h * D_ + lc);
        }
    };
    auto stkv = [&](int s) {
#pragma unroll
        for (int p = 0; p < 2; p++) {
            int r = p * 32 + lr;
            uint4 u = { hadd2u(rk[p].x, rs[p].x), hadd2u(rk[p].y, rs[p].y),
                        hadd2u(rk[p].z, rs[p].z), hadd2u(rk[p].w, rs[p].w) };
            *(uint4*)&Ks[s * (64 * 72) + r * 72 + lc] = u;
            *(uint4*)&Vs[s * (64 * 72) + r * 72 + lc] = rv[p];
        }
    };

    // ---- prefetch KV tile 0; Q -> smem with scale folded ----
    ldkv(0);
    const __half2 sc2 = __float2half2_rn(SCALE_);
#pragma unroll
    for (int p = 0; p < 4; p++) {
        int r = p * 32 + lr;
        uint4 q4 = *(const uint4*)(qkvg + (qbase + r) * C4_ + h * D_ + lc);
        q4.x = hmul2u(q4.x, sc2); q4.y = hmul2u(q4.y, sc2);
        q4.z = hmul2u(q4.z, sc2); q4.w = hmul2u(q4.w, sc2);
        *(uint4*)&Qs[r * 72 + lc] = q4;
    }
    __syncthreads();

    unsigned qf[4][4];
#pragma unroll
    for (int kd = 0; kd < 4; kd++)
        ldm_x4(qf[kd], &Qs[(wid * 16 + (lane & 15)) * 72 + kd * 16 + (lane >> 4) * 8]);
    stkv(0);
    __syncthreads();

    float o[8][4] = {};
    float m0v = -1e30f, m1v = -1e30f, l0v = 0.f, l1v = 0.f;

    for (int kt = 0; kt < N_ / 64; kt++) {
        const int cs = kt & 1;
        const __half* Kc = Ks + cs * (64 * 72);
        const __half* Vc = Vs + cs * (64 * 72);

        // ---- S = Q (K+s)^T : 16 x 64 per warp (scale pre-folded) ----
        float sc[8][4] = {};
#pragma unroll
        for (int kd = 0; kd < 4; kd++) {
            unsigned bf[8][2];
#pragma unroll
            for (int sp = 0; sp < 4; sp++) {
                unsigned tr[4];
                ldm_x4(tr, &Kc[(sp * 16 + (lane & 7) + (lane >> 4) * 8) * 72
                               + kd * 16 + ((lane >> 3) & 1) * 8]);
                bf[sp * 2 + 0][0] = tr[0]; bf[sp * 2 + 0][1] = tr[1];
                bf[sp * 2 + 1][0] = tr[2]; bf[sp * 2 + 1][1] = tr[3];
            }
#pragma unroll
            for (int nt = 0; nt < 8; nt++)
                mma_h(sc[nt], qf[kd], bf[nt]);
        }

        // ---- online softmax; P built directly as mma A-fragments ----
        float rmax0 = -1e30f, rmax1 = -1e30f;
#pragma unroll
        for (int nt = 0; nt < 8; nt++) {
            rmax0 = fmaxf(rmax0, fmaxf(sc[nt][0], sc[nt][1]));
            rmax1 = fmaxf(rmax1, fmaxf(sc[nt][2], sc[nt][3]));
        }
#pragma unroll
        for (int off = 1; off <= 2; off <<= 1) {
            rmax0 = fmaxf(rmax0, __shfl_xor_sync(~0u, rmax0, off));
            rmax1 = fmaxf(rmax1, __shfl_xor_sync(~0u, rmax1, off));
        }
        float mn0 = fmaxf(m0v, rmax0), mn1 = fmaxf(m1v, rmax1);
        float cf0 = __expf(m0v - mn0), cf1 = __expf(m1v - mn1);
        m0v = mn0; m1v = mn1;
        float rs0 = 0.f, rs1 = 0.f;
        unsigned pf[4][4];
#pragma unroll
        for (int nt = 0; nt < 8; nt++) {
            float p0 = __expf(sc[nt][0] - mn0);
            float p1 = __expf(sc[nt][1] - mn0);
            float p2 = __expf(sc[nt][2] - mn1);
            float p3 = __expf(sc[nt][3] - mn1);
            rs0 += p0 + p1; rs1 += p2 + p3;
            const int kk = nt >> 1, hi = (nt & 1) * 2;
            pf[kk][hi + 0] = h2u(__floats2half2_rn(p0, p1));  // row g
            pf[kk][hi + 1] = h2u(__floats2half2_rn(p2, p3));  // row g+8
        }
#pragma unroll
        for (int off = 1; off <= 2; off <<= 1) {
            rs0 += __shfl_xor_sync(~0u, rs0, off);
            rs1 += __shfl_xor_sync(~0u, rs1, off);
        }
        l0v = l0v * cf0 + rs0;
        l1v = l1v * cf1 + rs1;
#pragma unroll
        for (int nt = 0; nt < 8; nt++) {
            o[nt][0] *= cf0; o[nt][1] *= cf0;
            o[nt][2] *= cf1; o[nt][3] *= cf1;
        }

        // ---- prefetch next KV (sc regs dead; hidden under PV mma) ----
        if (kt + 1 < N_ / 64) ldkv(kt + 1);

        // ---- O += P V  (A fragments straight from registers) ----
#pragma unroll
        for (int kk = 0; kk < 4; kk++) {
            unsigned bf[8][2];
#pragma unroll
            for (int ds = 0; ds < 4; ds++) {
                unsigned tr[4];
                ldm_x4t(tr, &Vc[(kk * 16 + (lane & 7) + ((lane >> 3) & 1) * 8) * 72
                                + ds * 16 + (lane >> 4) * 8]);
                bf[ds * 2 + 0][0] = tr[0]; bf[ds * 2 + 0][1] = tr[1];
                bf[ds * 2 + 1][0] = tr[2]; bf[ds * 2 + 1][1] = tr[3];
            }
#pragma unroll
            for (int nt = 0; nt < 8; nt++)
                mma_h(o[nt], pf[kk], bf[nt]);
        }

        if (kt + 1 < N_ / 64) stkv((kt + 1) & 1);
        __syncthreads();
    }

    // ---- epilogue: normalize, gate (qkvg col 3C), write fp16 att ----
    const int g = lane >> 2, t = lane & 3;
    float inv0 = 1.f / l0v, inv1 = 1.f / l1v;
    size_t r0 = qbase + wid * 16 + g;
#pragma unroll
    for (int nt = 0; nt < 8; nt++) {
        int col = h * D_ + nt * 8 + 2 * t;
        float2 g0 = __half22float2(*(const __half2*)(qkvg + r0 * C4_ + 3 * C_ + col));
        float2 g1 = __half22float2(*(const __half2*)(qkvg + (r0 + 8) * C4_ + 3 * C_ + col));
        *(__half2*)(outp + r0 * C_ + col) =
            __floats2half2_rn(o[nt][0] * inv0 * g0.x, o[nt][1] * inv0 * g0.y);
        *(__half2*)(outp + (r0 + 8) * C_ + col) =
            __floats2half2_rn(o[nt][2] * inv1 * g1.x, o[nt][3] * inv1 * g1.y);
    }
}

// ---------------- launch ------------------------------------------------
extern "C" void kernel_launch(void* const* d_in, const int* in_sizes, int n_in,
                              void* d_out, int out_size)
{
    (void)in_sizes; (void)n_in; (void)out_size;
    const float* x    = (const float*)d_in[0];
    const float* e    = (const float*)d_in[1];
    const float* Wqkv = (const float*)d_in[2];
    const float* Ws   = (const float*)d_in[3];
    const float* Wg   = (const float*)d_in[4];
    const float* Wp   = (const float*)d_in[5];
    const float* bp   = (const float*)d_in[6];
    float* out = (float*)d_out;

    __half *xh, *eh, *wqkvgh, *wsh, *wph, *qkvgh, *sh, *atth;
    cudaGetSymbolAddress((void**)&xh,     g_x_h);
    cudaGetSymbolAddress((void**)&eh,     g_e_h);
    cudaGetSymbolAddress((void**)&wqkvgh, g_wqkvg_h);
    cudaGetSymbolAddress((void**)&wsh,    g_ws_h);
    cudaGetSymbolAddress((void**)&wph,    g_wp_h);
    cudaGetSymbolAddress((void**)&qkvgh,  g_qkvg_h);
    cudaGetSymbolAddress((void**)&sh,     g_s_h);
    cudaGetSymbolAddress((void**)&atth,   g_att_h);

    static int smem_set = 0;
    const int flash_smem = (128 + 2 * 64 + 2 * 64) * 72 * 2;
    if (!smem_set) {
        cudaFuncSetAttribute(flash_h, cudaFuncAttributeMaxDynamicSharedMemorySize, flash_smem);
        smem_set = 1;
    }

    // 1) all fp32->fp16 conversions in one launch
    cvt_all<<<14336, 256>>>(x, e, Wqkv, Wg, Ws, Wp, xh, eh, wqkvgh, wsh, wph);

    // 2) qkvg = x @ [Wqkv|Wgate]  AND  s = e @ W_s  in one launch
    gemm_fused<<<dim3(40, M_TOT / 128), 256>>>(xh, wqkvgh, qkvgh, eh, wsh, sh);

    // 3) fused flash attention (k+s fold, scale fold, gate fold, P in regs)
    flash_h<<<dim3(N_ / 128, H_, B_), 256, flash_smem>>>(qkvgh, sh, atth);

    // 4) out = att @ W_proj + b_proj
    gemm_proj<<<dim3(C_ / 128, M_TOT / 128), 256>>>(atth, wph, bp, out);
}